// round 5
// baseline (speedup 1.0000x reference)
#include <cuda_runtime.h>
#include <math.h>

constexpr int NNODE = 8192;
constexpr int NEDGE = 98304;
constexpr int EPB   = 16;

constexpr float SQRT3     = 1.7320508075688772f;
constexpr float INV_SQRT3 = 0.5773502691896258f;
constexpr float NORM24    = 0.20412414523193154f;  // 1/sqrt(24)
constexpr float INV_SQRT8 = 0.35355339059327373f;
constexpr float CEMB      = 1.14136f * 7.389056098930650f * 3.1622776601683795f;
constexpr float EMB_STEP  = 3.0f / 11.0f;
constexpr float INV_STEP  = 11.0f / 3.0f;

__device__ float g_qk0[NNODE * 16];
__device__ float g_qk1[NNODE * 24];
__device__ float g_z[NNODE];
__device__ float g_pot3[NNODE * 3];
__device__ float g_expv[NEDGE];
__device__ float g_cutw[NEDGE];
__device__ float g_sh1[NEDGE * 3];
__device__ float g_vflat[NEDGE * 40];
__device__ float g_wp[NEDGE * 72];

__device__ __forceinline__ float sus(float x) {
    return x > 0.f ? __expf(-1.f / x) : 0.f;
}

// ---------------- zero scratch + output ----------------
__global__ void kZero(float* __restrict__ out) {
    int i = blockIdx.x * blockDim.x + threadIdx.x;
    if (i < NNODE * 40) out[i] = 0.f;
    if (i < NNODE) g_z[i] = 0.f;
    if (i < NNODE * 3) g_pot3[i] = 0.f;
}

// ---------------- per-node qk precompute ----------------
__global__ void kQK(const float* __restrict__ feats,
                    const float* __restrict__ Wq0, const float* __restrict__ Wq1,
                    const float* __restrict__ Wd00, const float* __restrict__ Wd11) {
    int nd = blockIdx.x * blockDim.x + threadIdx.x;
    if (nd >= NNODE) return;
    const float* f = &feats[(size_t)nd * 40];
    float q0[16];
#pragma unroll
    for (int o = 0; o < 16; o++) {
        float a = 0.f;
#pragma unroll
        for (int i = 0; i < 16; i++) a += f[i] * __ldg(&Wq0[i * 16 + o]);
        q0[o] = a * 0.25f;
    }
#pragma unroll
    for (int j = 0; j < 16; j++) {
        float a = 0.f;
#pragma unroll
        for (int i = 0; i < 16; i++) a += q0[i] * __ldg(&Wd00[i * 16 + j]);
        g_qk0[(size_t)nd * 16 + j] = a;
    }
    float q1[24];
#pragma unroll
    for (int o = 0; o < 8; o++)
#pragma unroll
        for (int d = 0; d < 3; d++) {
            float a = 0.f;
#pragma unroll
            for (int i = 0; i < 8; i++) a += f[16 + i * 3 + d] * __ldg(&Wq1[i * 8 + o]);
            q1[o * 3 + d] = a * INV_SQRT8;
        }
#pragma unroll
    for (int j = 0; j < 8; j++)
#pragma unroll
        for (int d = 0; d < 3; d++) {
            float a = 0.f;
#pragma unroll
            for (int i = 0; i < 8; i++) a += q1[i * 3 + d] * __ldg(&Wd11[i * 8 + j]);
            g_qk1[(size_t)nd * 24 + j * 3 + d] = a;
        }
}

// ---------------- (16e x 32c) @ (32c x 576) GEMM, 2 edges/warp ----------------
__device__ __forceinline__ void gemm576(const float* __restrict__ W2,
                                        const float* __restrict__ s_H, int chOff,
                                        float* __restrict__ s_w, int lane, int ebase) {
    float acc[2][18];
#pragma unroll
    for (int s = 0; s < 2; s++)
#pragma unroll
        for (int j = 0; j < 18; j++) acc[s][j] = 0.f;
#pragma unroll 2
    for (int c = 0; c < 32; c++) {
        const float* row = W2 + c * 576;
        const float4* r4 = (const float4*)(row + 16 * lane);
        float4 w0 = __ldg(r4 + 0);
        float4 w1 = __ldg(r4 + 1);
        float4 w2 = __ldg(r4 + 2);
        float4 w3 = __ldg(r4 + 3);
        float2 w4 = __ldg((const float2*)(row + 512 + 2 * lane));
#pragma unroll
        for (int s = 0; s < 2; s++) {
            float h = s_H[(ebase + s) * 128 + chOff + c];
            acc[s][0]  += h * w0.x; acc[s][1]  += h * w0.y; acc[s][2]  += h * w0.z; acc[s][3]  += h * w0.w;
            acc[s][4]  += h * w1.x; acc[s][5]  += h * w1.y; acc[s][6]  += h * w1.z; acc[s][7]  += h * w1.w;
            acc[s][8]  += h * w2.x; acc[s][9]  += h * w2.y; acc[s][10] += h * w2.z; acc[s][11] += h * w2.w;
            acc[s][12] += h * w3.x; acc[s][13] += h * w3.y; acc[s][14] += h * w3.z; acc[s][15] += h * w3.w;
            acc[s][16] += h * w4.x; acc[s][17] += h * w4.y;
        }
    }
#pragma unroll
    for (int s = 0; s < 2; s++) {
        float* row = s_w + (ebase + s) * 576;
        float4* o4 = (float4*)(row + 16 * lane);
        o4[0] = make_float4(acc[s][0],  acc[s][1],  acc[s][2],  acc[s][3]);
        o4[1] = make_float4(acc[s][4],  acc[s][5],  acc[s][6],  acc[s][7]);
        o4[2] = make_float4(acc[s][8],  acc[s][9],  acc[s][10], acc[s][11]);
        o4[3] = make_float4(acc[s][12], acc[s][13], acc[s][14], acc[s][15]);
        *(float2*)(row + 512 + 2 * lane) = make_float2(acc[s][16], acc[s][17]);
    }
}

// smem float offsets (EPB=16)
constexpr int OFF_W   = 0;       // 16*576
constexpr int OFF_H   = 9216;    // 16*128
constexpr int OFF_X0  = 11264;   // 16*24  (x0[16] + x1s[8])
constexpr int OFF_X1  = 11648;   // 16*24
constexpr int OFF_QK0 = 12032;   // 16*16
constexpr int OFF_QK1 = 12288;   // 16*24
constexpr int OFF_EMB = 12672;   // 16*10
constexpr int OFF_SH  = 12832;   // 16*3
constexpr int OFF_CUT = 12880;   // 16
constexpr int OFF_IDX = 12896;   // 32 ints
constexpr int SMEM_FLOATS = 12928;

__global__ void __launch_bounds__(256)
kEdgeMain(const float* __restrict__ feats, const float* __restrict__ pos,
          const int* __restrict__ esrc, const int* __restrict__ edst,
          const float* __restrict__ W1k, const float* __restrict__ W2k,
          const float* __restrict__ W1v, const float* __restrict__ W2v,
          const float* __restrict__ W1p, const float* __restrict__ W2p) {
    extern __shared__ float sm[];
    float* s_w   = sm + OFF_W;
    float* s_H   = sm + OFF_H;
    float* s_X0  = sm + OFF_X0;
    float* s_x1  = sm + OFF_X1;
    float* s_qk0 = sm + OFF_QK0;
    float* s_qk1 = sm + OFF_QK1;
    float* s_emb = sm + OFF_EMB;
    float* s_sh  = sm + OFF_SH;
    float* s_cut = sm + OFF_CUT;
    int*   s_src = (int*)(sm + OFF_IDX);
    int*   s_dst = (int*)(sm + OFF_IDX + 16);

    const int tid  = threadIdx.x;
    const int lane = tid & 31;
    const int warp = tid >> 5;
    const int e0   = blockIdx.x * EPB;

    // phase 1: per-edge scalars
    if (tid < EPB) {
        int e = e0 + tid;
        int s = esrc[e], d = edst[e];
        s_src[tid] = s; s_dst[tid] = d;
        float vx = pos[s * 3 + 0] - pos[d * 3 + 0];
        float vy = pos[s * 3 + 1] - pos[d * 3 + 1];
        float vz = pos[s * 3 + 2] - pos[d * 3 + 2];
        float elen = sqrtf(vx * vx + vy * vy + vz * vz + 1e-12f);
        float invl = SQRT3 / elen;
        float shx = vx * invl, shy = vy * invl, shz = vz * invl;
        s_sh[tid * 3 + 0] = shx; s_sh[tid * 3 + 1] = shy; s_sh[tid * 3 + 2] = shz;
        g_sh1[(size_t)e * 3 + 0] = shx; g_sh1[(size_t)e * 3 + 1] = shy; g_sh1[(size_t)e * 3 + 2] = shz;
        float cut = sus(10.f * (1.f - elen * (1.f / 3.f)));
        s_cut[tid] = cut;
        g_cutw[e] = cut;
#pragma unroll
        for (int b = 0; b < 10; b++) {
            float diff = (elen - EMB_STEP * (float)(b + 1)) * INV_STEP;
            s_emb[tid * 10 + b] = CEMB * sus(diff + 1.f) * sus(1.f - diff);
        }
    }
    __syncthreads();

    // phase 2: gather node data
    {
        int e = tid >> 4, i = tid & 15;     // 256 = 16*16
        s_X0[e * 24 + i]  = feats[(size_t)s_src[e] * 40 + i];
        s_qk0[e * 16 + i] = g_qk0[(size_t)s_dst[e] * 16 + i];
    }
    for (int idx = tid; idx < 16 * 24; idx += 256) {
        int e = idx / 24, i = idx % 24;
        s_x1[e * 24 + i]  = feats[(size_t)s_src[e] * 40 + 16 + i];
        s_qk1[e * 24 + i] = g_qk1[(size_t)s_dst[e] * 24 + i];
    }
    __syncthreads();

    // phase 3a: x1s
    if (tid < 128) {
        int e = tid >> 3, i = tid & 7;
        const float* xp = &s_x1[e * 24 + i * 3];
        s_X0[e * 24 + 16 + i] =
            (xp[0] * s_sh[e * 3] + xp[1] * s_sh[e * 3 + 1] + xp[2] * s_sh[e * 3 + 2]) * INV_SQRT3;
    }
    // phase 3b: H = silu(emb @ W1) for k(32) | v(32) | p(64)
#pragma unroll 1
    for (int r = 0; r < 8; r++) {
        int id = r * 256 + tid;
        int e = id & 15, ch = id >> 4;
        const float* W1; int cc, ld;
        if (ch < 32)      { W1 = W1k; cc = ch;      ld = 32; }
        else if (ch < 64) { W1 = W1v; cc = ch - 32; ld = 32; }
        else              { W1 = W1p; cc = ch - 64; ld = 64; }
        float a = 0.f;
#pragma unroll
        for (int b = 0; b < 10; b++) a += s_emb[e * 10 + b] * __ldg(&W1[b * ld + cc]);
        s_H[e * 128 + ch] = a / (1.f + __expf(-a));
    }
    __syncthreads();

    const int ebase = warp * 2;

    // ===== K path =====
    gemm576(W2k, s_H, 0, s_w, lane, ebase);
    __syncthreads();
#pragma unroll 1
    for (int s2 = 0; s2 < 2; s2++) {
        int e = ebase + s2;
        const float* w  = s_w + e * 576;
        const float* X0 = s_X0 + e * 24;
        float partial = 0.f;
        if (lane < 16) {
            int o = lane;
            float k0 = 0.f;
#pragma unroll
            for (int i = 0; i < 16; i++) k0 += X0[i] * w[i * 16 + o];
#pragma unroll
            for (int i = 0; i < 8; i++)  k0 += X0[16 + i] * w[256 + i * 16 + o];
            partial = k0 * NORM24 * s_qk0[e * 16 + o];
        } else if (lane < 24) {
            int o = lane - 16;
            float xw = 0.f;
#pragma unroll
            for (int i = 0; i < 16; i++) xw += X0[i] * w[384 + i * 8 + o];
            float t = 0.f;
#pragma unroll
            for (int d = 0; d < 3; d++) {
                float k1 = 0.f;
#pragma unroll
                for (int i = 0; i < 8; i++) k1 += s_x1[e * 24 + i * 3 + d] * w[512 + i * 8 + o];
                k1 = (xw * s_sh[e * 3 + d] * INV_SQRT3 + k1) * NORM24;
                t += k1 * s_qk1[e * 24 + o * 3 + d];
            }
            partial = t * INV_SQRT3;
        }
#pragma unroll
        for (int off = 16; off; off >>= 1)
            partial += __shfl_xor_sync(0xffffffffu, partial, off);
        if (lane == 0) {
            float dot = partial * NORM24;
            float ev = s_cut[e] * expf(dot);
            g_expv[e0 + e] = ev;
            atomicAdd(&g_z[s_dst[e]], ev);
        }
    }
    __syncthreads();

    // ===== V path =====
    gemm576(W2v, s_H, 32, s_w, lane, ebase);
    __syncthreads();
#pragma unroll 1
    for (int s2 = 0; s2 < 2; s2++) {
        int e = ebase + s2;
        const float* w  = s_w + e * 576;
        const float* X0 = s_X0 + e * 24;
        float* vf = &g_vflat[(size_t)(e0 + e) * 40];
        if (lane < 16) {
            int o = lane;
            float v0 = 0.f;
#pragma unroll
            for (int i = 0; i < 16; i++) v0 += X0[i] * w[i * 16 + o];
#pragma unroll
            for (int i = 0; i < 8; i++)  v0 += X0[16 + i] * w[256 + i * 16 + o];
            vf[o] = v0 * NORM24;
        } else if (lane < 24) {
            int o = lane - 16;
            float xw = 0.f;
#pragma unroll
            for (int i = 0; i < 16; i++) xw += X0[i] * w[384 + i * 8 + o];
#pragma unroll
            for (int d = 0; d < 3; d++) {
                float v1 = 0.f;
#pragma unroll
                for (int i = 0; i < 8; i++) v1 += s_x1[e * 24 + i * 3 + d] * w[512 + i * 8 + o];
                v1 = (xw * s_sh[e * 3 + d] * INV_SQRT3 + v1) * NORM24;
                vf[16 + o * 3 + d] = v1;
            }
        }
    }
    __syncthreads();

    // ===== P path: only 72 of 1152 W2p columns are live =====
    for (int idx = tid; idx < 64 * 72; idx += 256) {
        int c = idx / 72, j = idx % 72;
        int jj   = (j < 48) ? j : j - 48;
        int base = (j < 48) ? 0 : 512;
        int col  = base + (jj / 3) * 32 + (jj % 3);
        s_w[c * 72 + j] = __ldg(&W2p[c * 1152 + col]);
    }
    __syncthreads();
    {
        float pa0[2] = {0, 0}, pa1[2] = {0, 0}, pa2[2] = {0, 0};
#pragma unroll 2
        for (int c = 0; c < 64; c++) {
            float w0 = s_w[c * 72 + lane];
            float w1 = s_w[c * 72 + 32 + lane];
            float w2 = (lane < 8) ? s_w[c * 72 + 64 + lane] : 0.f;
#pragma unroll
            for (int s2 = 0; s2 < 2; s2++) {
                float h = s_H[(ebase + s2) * 128 + 64 + c];
                pa0[s2] += h * w0; pa1[s2] += h * w1; pa2[s2] += h * w2;
            }
        }
#pragma unroll
        for (int s2 = 0; s2 < 2; s2++) {
            size_t e = (size_t)(e0 + ebase + s2);
            g_wp[e * 72 + lane]      = pa0[s2];
            g_wp[e * 72 + 32 + lane] = pa1[s2];
            if (lane < 8) g_wp[e * 72 + 64 + lane] = pa2[s2];
        }
    }
}

// ---------------- softmax + scatter att ----------------
__global__ void kAttScatter(const int* __restrict__ edst, float* __restrict__ out) {
    int idx = blockIdx.x * blockDim.x + threadIdx.x;
    if (idx >= NEDGE * 40) return;
    int e = idx / 40, j = idx - e * 40;
    int d = edst[e];
    float z = g_z[d];
    float zz = (z == 0.f) ? 1.f : z;
    float alpha = g_expv[e] / zz;
    float coef = (alpha > 0.f) ? sqrtf(alpha) : 0.f;
    if (coef != 0.f)
        atomicAdd(&out[(size_t)d * 40 + j], coef * g_vflat[(size_t)e * 40 + j]);
}

// ---------------- p pass (only p0 cols 0..2) ----------------
__global__ void kPEdge(const int* __restrict__ esrc, const int* __restrict__ edst,
                       const float* __restrict__ att) {
    int e = blockIdx.x * blockDim.x + threadIdx.x;
    if (e >= NEDGE) return;
    int s = esrc[e], d = edst[e];
    const float* a  = &att[(size_t)s * 40];
    const float* wp = &g_wp[(size_t)e * 72];
    float shx = g_sh1[(size_t)e * 3 + 0];
    float shy = g_sh1[(size_t)e * 3 + 1];
    float shz = g_sh1[(size_t)e * 3 + 2];
    float p0 = 0.f, p1 = 0.f, p2 = 0.f;
#pragma unroll
    for (int i = 0; i < 16; i++) {
        float ai = a[i];
        p0 += ai * wp[i * 3 + 0];
        p1 += ai * wp[i * 3 + 1];
        p2 += ai * wp[i * 3 + 2];
    }
#pragma unroll
    for (int i = 0; i < 8; i++) {
        float as = (a[16 + i * 3] * shx + a[16 + i * 3 + 1] * shy + a[16 + i * 3 + 2] * shz) * INV_SQRT3;
        p0 += as * wp[48 + i * 3 + 0];
        p1 += as * wp[48 + i * 3 + 1];
        p2 += as * wp[48 + i * 3 + 2];
    }
    float cw = g_cutw[e] * NORM24;
    atomicAdd(&g_pot3[(size_t)d * 3 + 0], cw * p0);
    atomicAdd(&g_pot3[(size_t)d * 3 + 1], cw * p1);
    atomicAdd(&g_pot3[(size_t)d * 3 + 2], cw * p2);
}

// ---------------- curl fixup ----------------
__global__ void kCurl(float* __restrict__ out) {
    int n = blockIdx.x * blockDim.x + threadIdx.x;
    if (n >= NNODE) return;
    float p0 = g_pot3[(size_t)n * 3 + 0];
    float p1 = g_pot3[(size_t)n * 3 + 1];
    float p2 = g_pot3[(size_t)n * 3 + 2];
    out[(size_t)n * 40 + 0] += 0.1f * (p2 - p1);
    out[(size_t)n * 40 + 1] += 0.1f * (p0 - p2);
    out[(size_t)n * 40 + 2] += 0.1f * (p1 - p0);
}

extern "C" void kernel_launch(void* const* d_in, const int* in_sizes, int n_in,
                              void* d_out, int out_size) {
    const float* feats = (const float*)d_in[0];
    const float* pos   = (const float*)d_in[1];
    const int*   esrc  = (const int*)d_in[2];
    const int*   edst  = (const int*)d_in[3];
    const float* Wq0   = (const float*)d_in[4];
    const float* Wq1   = (const float*)d_in[5];
    const float* W1k   = (const float*)d_in[6];
    const float* W2k   = (const float*)d_in[7];
    const float* W1v   = (const float*)d_in[8];
    const float* W2v   = (const float*)d_in[9];
    const float* Wd00  = (const float*)d_in[10];
    const float* Wd11  = (const float*)d_in[11];
    const float* W1p   = (const float*)d_in[12];
    const float* W2p   = (const float*)d_in[13];
    float* out = (float*)d_out;

    const int smem_bytes = SMEM_FLOATS * 4;
    cudaFuncSetAttribute(kEdgeMain, cudaFuncAttributeMaxDynamicSharedMemorySize, smem_bytes);

    kZero<<<(NNODE * 40 + 255) / 256, 256>>>(out);
    kQK<<<(NNODE + 255) / 256, 256>>>(feats, Wq0, Wq1, Wd00, Wd11);
    kEdgeMain<<<NEDGE / EPB, 256, smem_bytes>>>(feats, pos, esrc, edst,
                                                W1k, W2k, W1v, W2v, W1p, W2p);
    kAttScatter<<<(NEDGE * 40 + 255) / 256, 256>>>(edst, out);
    kPEdge<<<(NEDGE + 255) / 256, 256>>>(esrc, edst, out);
    kCurl<<<(NNODE + 255) / 256, 256>>>(out);
}

// round 6
// speedup vs baseline: 1.4595x; 1.4595x over previous
#include <cuda_runtime.h>
#include <math.h>

constexpr int NNODE = 8192;
constexpr int NEDGE = 98304;
constexpr int EPB   = 32;

constexpr float SQRT3     = 1.7320508075688772f;
constexpr float INV_SQRT3 = 0.5773502691896258f;
constexpr float NORM24    = 0.20412414523193154f;  // 1/sqrt(24)
constexpr float INV_SQRT8 = 0.35355339059327373f;
constexpr float CEMB      = 1.14136f * 7.389056098930650f * 3.1622776601683795f;
constexpr float EMB_STEP  = 3.0f / 11.0f;
constexpr float INV_STEP  = 11.0f / 3.0f;

__device__ float g_qk0[NNODE * 16];
__device__ float g_qk1[NNODE * 24];
__device__ float g_z[NNODE];
__device__ float g_pot3[NNODE * 3];
__device__ float g_expv[NEDGE];
__device__ float g_cutw[NEDGE];
__device__ float g_sh1[NEDGE * 3];
__device__ float g_vflat[NEDGE * 40];
__device__ float g_wp[NEDGE * 72];

__device__ __forceinline__ float sus(float x) {
    return x > 0.f ? __expf(-1.f / x) : 0.f;
}

// ---------------- zero scratch + output ----------------
__global__ void kZero(float* __restrict__ out) {
    int i = blockIdx.x * blockDim.x + threadIdx.x;
    if (i < NNODE * 40) out[i] = 0.f;
    if (i < NNODE) g_z[i] = 0.f;
    if (i < NNODE * 3) g_pot3[i] = 0.f;
}

// ---------------- per-node qk precompute ----------------
__global__ void kQK(const float* __restrict__ feats,
                    const float* __restrict__ Wq0, const float* __restrict__ Wq1,
                    const float* __restrict__ Wd00, const float* __restrict__ Wd11) {
    int nd = blockIdx.x * blockDim.x + threadIdx.x;
    if (nd >= NNODE) return;
    const float* f = &feats[(size_t)nd * 40];
    float q0[16];
#pragma unroll
    for (int o = 0; o < 16; o++) {
        float a = 0.f;
#pragma unroll
        for (int i = 0; i < 16; i++) a += f[i] * __ldg(&Wq0[i * 16 + o]);
        q0[o] = a * 0.25f;
    }
#pragma unroll
    for (int j = 0; j < 16; j++) {
        float a = 0.f;
#pragma unroll
        for (int i = 0; i < 16; i++) a += q0[i] * __ldg(&Wd00[i * 16 + j]);
        g_qk0[(size_t)nd * 16 + j] = a;
    }
    float q1[24];
#pragma unroll
    for (int o = 0; o < 8; o++)
#pragma unroll
        for (int d = 0; d < 3; d++) {
            float a = 0.f;
#pragma unroll
            for (int i = 0; i < 8; i++) a += f[16 + i * 3 + d] * __ldg(&Wq1[i * 8 + o]);
            q1[o * 3 + d] = a * INV_SQRT8;
        }
#pragma unroll
    for (int j = 0; j < 8; j++)
#pragma unroll
        for (int d = 0; d < 3; d++) {
            float a = 0.f;
#pragma unroll
            for (int i = 0; i < 8; i++) a += q1[i * 3 + d] * __ldg(&Wd11[i * 8 + j]);
            g_qk1[(size_t)nd * 24 + j * 3 + d] = a;
        }
}

// ---------------- (32e x 32c) @ (32c x 576) GEMM, 4 edges/warp ----------------
__device__ __forceinline__ void gemm576(const float* __restrict__ W2,
                                        const float* __restrict__ s_H, int chOff,
                                        float* __restrict__ s_w, int lane, int ebase) {
    float acc[4][18];
#pragma unroll
    for (int s = 0; s < 4; s++)
#pragma unroll
        for (int j = 0; j < 18; j++) acc[s][j] = 0.f;
#pragma unroll 2
    for (int c = 0; c < 32; c++) {
        const float* row = W2 + c * 576;
        const float4* r4 = (const float4*)(row + 16 * lane);
        float4 w0 = __ldg(r4 + 0);
        float4 w1 = __ldg(r4 + 1);
        float4 w2 = __ldg(r4 + 2);
        float4 w3 = __ldg(r4 + 3);
        float2 w4 = __ldg((const float2*)(row + 512 + 2 * lane));
        float h0 = s_H[(ebase + 0) * 128 + chOff + c];
        float h1 = s_H[(ebase + 1) * 128 + chOff + c];
        float h2 = s_H[(ebase + 2) * 128 + chOff + c];
        float h3 = s_H[(ebase + 3) * 128 + chOff + c];
        float hh[4] = {h0, h1, h2, h3};
#pragma unroll
        for (int s = 0; s < 4; s++) {
            float h = hh[s];
            acc[s][0]  += h * w0.x; acc[s][1]  += h * w0.y; acc[s][2]  += h * w0.z; acc[s][3]  += h * w0.w;
            acc[s][4]  += h * w1.x; acc[s][5]  += h * w1.y; acc[s][6]  += h * w1.z; acc[s][7]  += h * w1.w;
            acc[s][8]  += h * w2.x; acc[s][9]  += h * w2.y; acc[s][10] += h * w2.z; acc[s][11] += h * w2.w;
            acc[s][12] += h * w3.x; acc[s][13] += h * w3.y; acc[s][14] += h * w3.z; acc[s][15] += h * w3.w;
            acc[s][16] += h * w4.x; acc[s][17] += h * w4.y;
        }
    }
#pragma unroll
    for (int s = 0; s < 4; s++) {
        float* row = s_w + (ebase + s) * 576;
        float4* o4 = (float4*)(row + 16 * lane);
        o4[0] = make_float4(acc[s][0],  acc[s][1],  acc[s][2],  acc[s][3]);
        o4[1] = make_float4(acc[s][4],  acc[s][5],  acc[s][6],  acc[s][7]);
        o4[2] = make_float4(acc[s][8],  acc[s][9],  acc[s][10], acc[s][11]);
        o4[3] = make_float4(acc[s][12], acc[s][13], acc[s][14], acc[s][15]);
        *(float2*)(row + 512 + 2 * lane) = make_float2(acc[s][16], acc[s][17]);
    }
}

// smem float offsets (EPB=32)
constexpr int OFF_W   = 0;        // 32*576 = 18432
constexpr int OFF_H   = 18432;    // 32*128 = 4096
constexpr int OFF_X0  = 22528;    // 32*24 (x0[16] + x1s[8])
constexpr int OFF_X1  = 23296;    // 32*24
constexpr int OFF_QK0 = 24064;    // 32*16
constexpr int OFF_QK1 = 24576;    // 32*24
constexpr int OFF_EMB = 25344;    // 32*10
constexpr int OFF_SH  = 25664;    // 32*3
constexpr int OFF_CUT = 25760;    // 32
constexpr int OFF_IDX = 25792;    // 64 ints
constexpr int SMEM_FLOATS = 25856;

__global__ void __launch_bounds__(256, 2)
kEdgeMain(const float* __restrict__ feats, const float* __restrict__ pos,
          const int* __restrict__ esrc, const int* __restrict__ edst,
          const float* __restrict__ W1k, const float* __restrict__ W2k,
          const float* __restrict__ W1v, const float* __restrict__ W2v,
          const float* __restrict__ W1p, const float* __restrict__ W2p) {
    extern __shared__ float sm[];
    float* s_w   = sm + OFF_W;
    float* s_H   = sm + OFF_H;
    float* s_X0  = sm + OFF_X0;
    float* s_x1  = sm + OFF_X1;
    float* s_qk0 = sm + OFF_QK0;
    float* s_qk1 = sm + OFF_QK1;
    float* s_emb = sm + OFF_EMB;
    float* s_sh  = sm + OFF_SH;
    float* s_cut = sm + OFF_CUT;
    int*   s_src = (int*)(sm + OFF_IDX);
    int*   s_dst = (int*)(sm + OFF_IDX + 32);

    const int tid  = threadIdx.x;
    const int lane = tid & 31;
    const int warp = tid >> 5;
    const int e0   = blockIdx.x * EPB;

    // phase 1: per-edge scalars
    if (tid < EPB) {
        int e = e0 + tid;
        int s = esrc[e], d = edst[e];
        s_src[tid] = s; s_dst[tid] = d;
        float vx = pos[s * 3 + 0] - pos[d * 3 + 0];
        float vy = pos[s * 3 + 1] - pos[d * 3 + 1];
        float vz = pos[s * 3 + 2] - pos[d * 3 + 2];
        float elen = sqrtf(vx * vx + vy * vy + vz * vz + 1e-12f);
        float invl = SQRT3 / elen;
        float shx = vx * invl, shy = vy * invl, shz = vz * invl;
        s_sh[tid * 3 + 0] = shx; s_sh[tid * 3 + 1] = shy; s_sh[tid * 3 + 2] = shz;
        g_sh1[(size_t)e * 3 + 0] = shx; g_sh1[(size_t)e * 3 + 1] = shy; g_sh1[(size_t)e * 3 + 2] = shz;
        float cut = sus(10.f * (1.f - elen * (1.f / 3.f)));
        s_cut[tid] = cut;
        g_cutw[e] = cut;
#pragma unroll
        for (int b = 0; b < 10; b++) {
            float diff = (elen - EMB_STEP * (float)(b + 1)) * INV_STEP;
            s_emb[tid * 10 + b] = CEMB * sus(diff + 1.f) * sus(1.f - diff);
        }
    }
    __syncthreads();

    // phase 2: gather node data
    for (int idx = tid; idx < 32 * 16; idx += 256) {
        int e = idx >> 4, i = idx & 15;
        s_X0[e * 24 + i]  = feats[(size_t)s_src[e] * 40 + i];
        s_qk0[e * 16 + i] = g_qk0[(size_t)s_dst[e] * 16 + i];
    }
    for (int idx = tid; idx < 32 * 24; idx += 256) {
        int e = idx / 24, i = idx % 24;
        s_x1[e * 24 + i]  = feats[(size_t)s_src[e] * 40 + 16 + i];
        s_qk1[e * 24 + i] = g_qk1[(size_t)s_dst[e] * 24 + i];
    }
    __syncthreads();

    // phase 3a: x1s = (x1 . sh)/sqrt3  (256 threads = 32 edges x 8 i)
    {
        int e = tid >> 3, i = tid & 7;
        const float* xp = &s_x1[e * 24 + i * 3];
        s_X0[e * 24 + 16 + i] =
            (xp[0] * s_sh[e * 3] + xp[1] * s_sh[e * 3 + 1] + xp[2] * s_sh[e * 3 + 2]) * INV_SQRT3;
    }
    // phase 3b: H = silu(emb @ W1) for k(32) | v(32) | p(64)
#pragma unroll 1
    for (int r = 0; r < 16; r++) {
        int id = r * 256 + tid;
        int e = id & 31, ch = id >> 5;
        const float* W1; int cc, ld;
        if (ch < 32)      { W1 = W1k; cc = ch;      ld = 32; }
        else if (ch < 64) { W1 = W1v; cc = ch - 32; ld = 32; }
        else              { W1 = W1p; cc = ch - 64; ld = 64; }
        float a = 0.f;
#pragma unroll
        for (int b = 0; b < 10; b++) a += s_emb[e * 10 + b] * __ldg(&W1[b * ld + cc]);
        s_H[e * 128 + ch] = a / (1.f + __expf(-a));
    }
    __syncthreads();

    const int ebase = warp * 4;

    // ===== K path =====
    gemm576(W2k, s_H, 0, s_w, lane, ebase);
    __syncthreads();
#pragma unroll 1
    for (int s4 = 0; s4 < 4; s4++) {
        int e = ebase + s4;
        const float* w  = s_w + e * 576;
        const float* X0 = s_X0 + e * 24;
        float partial = 0.f;
        if (lane < 16) {
            int o = lane;
            float k0 = 0.f;
#pragma unroll
            for (int i = 0; i < 16; i++) k0 += X0[i] * w[i * 16 + o];
#pragma unroll
            for (int i = 0; i < 8; i++)  k0 += X0[16 + i] * w[256 + i * 16 + o];
            partial = k0 * NORM24 * s_qk0[e * 16 + o];
        } else if (lane < 24) {
            int o = lane - 16;
            float xw = 0.f;
#pragma unroll
            for (int i = 0; i < 16; i++) xw += X0[i] * w[384 + i * 8 + o];
            float t = 0.f;
#pragma unroll
            for (int d = 0; d < 3; d++) {
                float k1 = 0.f;
#pragma unroll
                for (int i = 0; i < 8; i++) k1 += s_x1[e * 24 + i * 3 + d] * w[512 + i * 8 + o];
                k1 = (xw * s_sh[e * 3 + d] * INV_SQRT3 + k1) * NORM24;
                t += k1 * s_qk1[e * 24 + o * 3 + d];
            }
            partial = t * INV_SQRT3;
        }
#pragma unroll
        for (int off = 16; off; off >>= 1)
            partial += __shfl_xor_sync(0xffffffffu, partial, off);
        if (lane == 0) {
            float dot = partial * NORM24;
            float ev = s_cut[e] * expf(dot);
            g_expv[e0 + e] = ev;
            atomicAdd(&g_z[s_dst[e]], ev);
        }
    }
    __syncthreads();

    // ===== V path =====
    gemm576(W2v, s_H, 32, s_w, lane, ebase);
    __syncthreads();
#pragma unroll 1
    for (int s4 = 0; s4 < 4; s4++) {
        int e = ebase + s4;
        const float* w  = s_w + e * 576;
        const float* X0 = s_X0 + e * 24;
        float* vf = &g_vflat[(size_t)(e0 + e) * 40];
        if (lane < 16) {
            int o = lane;
            float v0 = 0.f;
#pragma unroll
            for (int i = 0; i < 16; i++) v0 += X0[i] * w[i * 16 + o];
#pragma unroll
            for (int i = 0; i < 8; i++)  v0 += X0[16 + i] * w[256 + i * 16 + o];
            vf[o] = v0 * NORM24;
        } else if (lane < 24) {
            int o = lane - 16;
            float xw = 0.f;
#pragma unroll
            for (int i = 0; i < 16; i++) xw += X0[i] * w[384 + i * 8 + o];
#pragma unroll
            for (int d = 0; d < 3; d++) {
                float v1 = 0.f;
#pragma unroll
                for (int i = 0; i < 8; i++) v1 += s_x1[e * 24 + i * 3 + d] * w[512 + i * 8 + o];
                v1 = (xw * s_sh[e * 3 + d] * INV_SQRT3 + v1) * NORM24;
                vf[16 + o * 3 + d] = v1;
            }
        }
    }
    __syncthreads();

    // ===== P path: only 72 of 1152 W2p columns are live =====
    for (int idx = tid; idx < 64 * 72; idx += 256) {
        int c = idx / 72, j = idx % 72;
        int jj   = (j < 48) ? j : j - 48;
        int base = (j < 48) ? 0 : 512;
        int col  = base + (jj / 3) * 32 + (jj % 3);
        s_w[c * 72 + j] = __ldg(&W2p[c * 1152 + col]);
    }
    __syncthreads();
    {
        float pa0[4] = {0, 0, 0, 0}, pa1[4] = {0, 0, 0, 0}, pa2[4] = {0, 0, 0, 0};
#pragma unroll 2
        for (int c = 0; c < 64; c++) {
            float w0 = s_w[c * 72 + lane];
            float w1 = s_w[c * 72 + 32 + lane];
            float w2 = (lane < 8) ? s_w[c * 72 + 64 + lane] : 0.f;
#pragma unroll
            for (int s4 = 0; s4 < 4; s4++) {
                float h = s_H[(ebase + s4) * 128 + 64 + c];
                pa0[s4] += h * w0; pa1[s4] += h * w1; pa2[s4] += h * w2;
            }
        }
#pragma unroll
        for (int s4 = 0; s4 < 4; s4++) {
            size_t e = (size_t)(e0 + ebase + s4);
            g_wp[e * 72 + lane]      = pa0[s4];
            g_wp[e * 72 + 32 + lane] = pa1[s4];
            if (lane < 8) g_wp[e * 72 + 64 + lane] = pa2[s4];
        }
    }
}

// ---------------- softmax + scatter att ----------------
__global__ void kAttScatter(const int* __restrict__ edst, float* __restrict__ out) {
    int idx = blockIdx.x * blockDim.x + threadIdx.x;
    if (idx >= NEDGE * 40) return;
    int e = idx / 40, j = idx - e * 40;
    int d = edst[e];
    float z = g_z[d];
    float zz = (z == 0.f) ? 1.f : z;
    float alpha = g_expv[e] / zz;
    float coef = (alpha > 0.f) ? sqrtf(alpha) : 0.f;
    if (coef != 0.f)
        atomicAdd(&out[(size_t)d * 40 + j], coef * g_vflat[(size_t)e * 40 + j]);
}

// ---------------- p pass (only p0 cols 0..2 are live) ----------------
__global__ void kPEdge(const int* __restrict__ esrc, const int* __restrict__ edst,
                       const float* __restrict__ att) {
    int e = blockIdx.x * blockDim.x + threadIdx.x;
    if (e >= NEDGE) return;
    int s = esrc[e], d = edst[e];
    const float* a  = &att[(size_t)s * 40];
    const float* wp = &g_wp[(size_t)e * 72];
    float shx = g_sh1[(size_t)e * 3 + 0];
    float shy = g_sh1[(size_t)e * 3 + 1];
    float shz = g_sh1[(size_t)e * 3 + 2];
    float p0 = 0.f, p1 = 0.f, p2 = 0.f;
#pragma unroll
    for (int i = 0; i < 16; i++) {
        float ai = a[i];
        p0 += ai * wp[i * 3 + 0];
        p1 += ai * wp[i * 3 + 1];
        p2 += ai * wp[i * 3 + 2];
    }
#pragma unroll
    for (int i = 0; i < 8; i++) {
        float as = (a[16 + i * 3] * shx + a[16 + i * 3 + 1] * shy + a[16 + i * 3 + 2] * shz) * INV_SQRT3;
        p0 += as * wp[48 + i * 3 + 0];
        p1 += as * wp[48 + i * 3 + 1];
        p2 += as * wp[48 + i * 3 + 2];
    }
    float cw = g_cutw[e] * NORM24;
    atomicAdd(&g_pot3[(size_t)d * 3 + 0], cw * p0);
    atomicAdd(&g_pot3[(size_t)d * 3 + 1], cw * p1);
    atomicAdd(&g_pot3[(size_t)d * 3 + 2], cw * p2);
}

// ---------------- curl fixup ----------------
__global__ void kCurl(float* __restrict__ out) {
    int n = blockIdx.x * blockDim.x + threadIdx.x;
    if (n >= NNODE) return;
    float p0 = g_pot3[(size_t)n * 3 + 0];
    float p1 = g_pot3[(size_t)n * 3 + 1];
    float p2 = g_pot3[(size_t)n * 3 + 2];
    out[(size_t)n * 40 + 0] += 0.1f * (p2 - p1);
    out[(size_t)n * 40 + 1] += 0.1f * (p0 - p2);
    out[(size_t)n * 40 + 2] += 0.1f * (p1 - p0);
}

extern "C" void kernel_launch(void* const* d_in, const int* in_sizes, int n_in,
                              void* d_out, int out_size) {
    const float* feats = (const float*)d_in[0];
    const float* pos   = (const float*)d_in[1];
    const int*   esrc  = (const int*)d_in[2];
    const int*   edst  = (const int*)d_in[3];
    const float* Wq0   = (const float*)d_in[4];
    const float* Wq1   = (const float*)d_in[5];
    const float* W1k   = (const float*)d_in[6];
    const float* W2k   = (const float*)d_in[7];
    const float* W1v   = (const float*)d_in[8];
    const float* W2v   = (const float*)d_in[9];
    const float* Wd00  = (const float*)d_in[10];
    const float* Wd11  = (const float*)d_in[11];
    const float* W1p   = (const float*)d_in[12];
    const float* W2p   = (const float*)d_in[13];
    float* out = (float*)d_out;

    const int smem_bytes = SMEM_FLOATS * 4;
    cudaFuncSetAttribute(kEdgeMain, cudaFuncAttributeMaxDynamicSharedMemorySize, smem_bytes);

    kZero<<<(NNODE * 40 + 255) / 256, 256>>>(out);
    kQK<<<(NNODE + 255) / 256, 256>>>(feats, Wq0, Wq1, Wd00, Wd11);
    kEdgeMain<<<NEDGE / EPB, 256, smem_bytes>>>(feats, pos, esrc, edst,
                                                W1k, W2k, W1v, W2v, W1p, W2p);
    kAttScatter<<<(NEDGE * 40 + 255) / 256, 256>>>(edst, out);
    kPEdge<<<(NEDGE + 255) / 256, 256>>>(esrc, edst, out);
    kCurl<<<(NNODE + 255) / 256, 256>>>(out);
}

// round 7
// speedup vs baseline: 1.9335x; 1.3248x over previous
#include <cuda_runtime.h>
#include <math.h>

constexpr int NNODE = 8192;
constexpr int NEDGE = 98304;
constexpr int EPB   = 32;

constexpr float SQRT3     = 1.7320508075688772f;
constexpr float INV_SQRT3 = 0.5773502691896258f;
constexpr float NORM24    = 0.20412414523193154f;  // 1/sqrt(24)
constexpr float INV_SQRT8 = 0.35355339059327373f;
constexpr float CEMB      = 1.14136f * 7.389056098930650f * 3.1622776601683795f;
constexpr float EMB_STEP  = 3.0f / 11.0f;
constexpr float INV_STEP  = 11.0f / 3.0f;

__device__ float g_qk0[NNODE * 16];
__device__ float g_qk1[NNODE * 24];
__device__ float g_z[NNODE];
__device__ float g_pot3[NNODE * 3];
__device__ float g_expv[NEDGE];
__device__ float g_cutw[NEDGE];
__device__ float g_sh1[NEDGE * 3];
__device__ float g_vflat[NEDGE * 40];
__device__ float g_wp[NEDGE * 72];

__device__ __forceinline__ float sus(float x) {
    return x > 0.f ? __expf(-1.f / x) : 0.f;
}

// ---------------- zero scratch + output ----------------
__global__ void kZero(float* __restrict__ out) {
    int i = blockIdx.x * blockDim.x + threadIdx.x;
    if (i < NNODE * 40) out[i] = 0.f;
    if (i < NNODE) g_z[i] = 0.f;
    if (i < NNODE * 3) g_pot3[i] = 0.f;
}

// ---------------- per-node qk precompute ----------------
__global__ void kQK(const float* __restrict__ feats,
                    const float* __restrict__ Wq0, const float* __restrict__ Wq1,
                    const float* __restrict__ Wd00, const float* __restrict__ Wd11) {
    int nd = blockIdx.x * blockDim.x + threadIdx.x;
    if (nd >= NNODE) return;
    const float* f = &feats[(size_t)nd * 40];
    float q0[16];
#pragma unroll
    for (int o = 0; o < 16; o++) {
        float a = 0.f;
#pragma unroll
        for (int i = 0; i < 16; i++) a += f[i] * __ldg(&Wq0[i * 16 + o]);
        q0[o] = a * 0.25f;
    }
#pragma unroll
    for (int j = 0; j < 16; j++) {
        float a = 0.f;
#pragma unroll
        for (int i = 0; i < 16; i++) a += q0[i] * __ldg(&Wd00[i * 16 + j]);
        g_qk0[(size_t)nd * 16 + j] = a;
    }
    float q1[24];
#pragma unroll
    for (int o = 0; o < 8; o++)
#pragma unroll
        for (int d = 0; d < 3; d++) {
            float a = 0.f;
#pragma unroll
            for (int i = 0; i < 8; i++) a += f[16 + i * 3 + d] * __ldg(&Wq1[i * 8 + o]);
            q1[o * 3 + d] = a * INV_SQRT8;
        }
#pragma unroll
    for (int j = 0; j < 8; j++)
#pragma unroll
        for (int d = 0; d < 3; d++) {
            float a = 0.f;
#pragma unroll
            for (int i = 0; i < 8; i++) a += q1[i * 3 + d] * __ldg(&Wd11[i * 8 + j]);
            g_qk1[(size_t)nd * 24 + j * 3 + d] = a;
        }
}

// ---------------- (32e x 32c) @ (32c x 576) GEMM, 4 edges/warp ----------------
// Interleaved lane->column map: lane l owns float4s {l, l+32, l+64, l+96} of the
// 576-wide row plus float2 l of the tail 64 -> 16B/lane stride, nL=4 coalesced
// LDG.128 and conflict-free STS.128. s_w keeps canonical column layout.
__device__ __forceinline__ void gemm576(const float* __restrict__ W2,
                                        const float* __restrict__ s_H, int chOff,
                                        float* __restrict__ s_w, int lane, int ebase) {
    float acc[4][18];
#pragma unroll
    for (int s = 0; s < 4; s++)
#pragma unroll
        for (int j = 0; j < 18; j++) acc[s][j] = 0.f;
#pragma unroll 2
    for (int c = 0; c < 32; c++) {
        const float* row = W2 + c * 576;
        const float4* r4 = (const float4*)row;
        float4 w0 = __ldg(r4 + lane);
        float4 w1 = __ldg(r4 + lane + 32);
        float4 w2 = __ldg(r4 + lane + 64);
        float4 w3 = __ldg(r4 + lane + 96);
        float2 w4 = __ldg((const float2*)(row + 512) + lane);
        float h0 = s_H[(ebase + 0) * 128 + chOff + c];
        float h1 = s_H[(ebase + 1) * 128 + chOff + c];
        float h2 = s_H[(ebase + 2) * 128 + chOff + c];
        float h3 = s_H[(ebase + 3) * 128 + chOff + c];
        float hh[4] = {h0, h1, h2, h3};
#pragma unroll
        for (int s = 0; s < 4; s++) {
            float h = hh[s];
            acc[s][0]  += h * w0.x; acc[s][1]  += h * w0.y; acc[s][2]  += h * w0.z; acc[s][3]  += h * w0.w;
            acc[s][4]  += h * w1.x; acc[s][5]  += h * w1.y; acc[s][6]  += h * w1.z; acc[s][7]  += h * w1.w;
            acc[s][8]  += h * w2.x; acc[s][9]  += h * w2.y; acc[s][10] += h * w2.z; acc[s][11] += h * w2.w;
            acc[s][12] += h * w3.x; acc[s][13] += h * w3.y; acc[s][14] += h * w3.z; acc[s][15] += h * w3.w;
            acc[s][16] += h * w4.x; acc[s][17] += h * w4.y;
        }
    }
#pragma unroll
    for (int s = 0; s < 4; s++) {
        float* row = s_w + (ebase + s) * 576;
        float4* o4 = (float4*)row;
        o4[lane]      = make_float4(acc[s][0],  acc[s][1],  acc[s][2],  acc[s][3]);
        o4[lane + 32] = make_float4(acc[s][4],  acc[s][5],  acc[s][6],  acc[s][7]);
        o4[lane + 64] = make_float4(acc[s][8],  acc[s][9],  acc[s][10], acc[s][11]);
        o4[lane + 96] = make_float4(acc[s][12], acc[s][13], acc[s][14], acc[s][15]);
        ((float2*)(row + 512))[lane] = make_float2(acc[s][16], acc[s][17]);
    }
}

// smem float offsets (EPB=32)
constexpr int OFF_W   = 0;        // 32*576 = 18432
constexpr int OFF_H   = 18432;    // 32*128 = 4096
constexpr int OFF_X0  = 22528;    // 32*24 (x0[16] + x1s[8])
constexpr int OFF_X1  = 23296;    // 32*24
constexpr int OFF_QK0 = 24064;    // 32*16
constexpr int OFF_QK1 = 24576;    // 32*24
constexpr int OFF_EMB = 25344;    // 32*10
constexpr int OFF_SH  = 25664;    // 32*3
constexpr int OFF_CUT = 25760;    // 32
constexpr int OFF_IDX = 25792;    // 64 ints
constexpr int SMEM_FLOATS = 25856;

__global__ void __launch_bounds__(256, 2)
kEdgeMain(const float* __restrict__ feats, const float* __restrict__ pos,
          const int* __restrict__ esrc, const int* __restrict__ edst,
          const float* __restrict__ W1k, const float* __restrict__ W2k,
          const float* __restrict__ W1v, const float* __restrict__ W2v,
          const float* __restrict__ W1p, const float* __restrict__ W2p) {
    extern __shared__ float sm[];
    float* s_w   = sm + OFF_W;
    float* s_H   = sm + OFF_H;
    float* s_X0  = sm + OFF_X0;
    float* s_x1  = sm + OFF_X1;
    float* s_qk0 = sm + OFF_QK0;
    float* s_qk1 = sm + OFF_QK1;
    float* s_emb = sm + OFF_EMB;
    float* s_sh  = sm + OFF_SH;
    float* s_cut = sm + OFF_CUT;
    int*   s_src = (int*)(sm + OFF_IDX);
    int*   s_dst = (int*)(sm + OFF_IDX + 32);

    const int tid  = threadIdx.x;
    const int lane = tid & 31;
    const int warp = tid >> 5;
    const int e0   = blockIdx.x * EPB;

    // phase 1: per-edge scalars
    if (tid < EPB) {
        int e = e0 + tid;
        int s = esrc[e], d = edst[e];
        s_src[tid] = s; s_dst[tid] = d;
        float vx = pos[s * 3 + 0] - pos[d * 3 + 0];
        float vy = pos[s * 3 + 1] - pos[d * 3 + 1];
        float vz = pos[s * 3 + 2] - pos[d * 3 + 2];
        float elen = sqrtf(vx * vx + vy * vy + vz * vz + 1e-12f);
        float invl = SQRT3 / elen;
        float shx = vx * invl, shy = vy * invl, shz = vz * invl;
        s_sh[tid * 3 + 0] = shx; s_sh[tid * 3 + 1] = shy; s_sh[tid * 3 + 2] = shz;
        g_sh1[(size_t)e * 3 + 0] = shx; g_sh1[(size_t)e * 3 + 1] = shy; g_sh1[(size_t)e * 3 + 2] = shz;
        float cut = sus(10.f * (1.f - elen * (1.f / 3.f)));
        s_cut[tid] = cut;
        g_cutw[e] = cut;
#pragma unroll
        for (int b = 0; b < 10; b++) {
            float diff = (elen - EMB_STEP * (float)(b + 1)) * INV_STEP;
            s_emb[tid * 10 + b] = CEMB * sus(diff + 1.f) * sus(1.f - diff);
        }
    }
    __syncthreads();

    // phase 2: gather node data
    for (int idx = tid; idx < 32 * 16; idx += 256) {
        int e = idx >> 4, i = idx & 15;
        s_X0[e * 24 + i]  = feats[(size_t)s_src[e] * 40 + i];
        s_qk0[e * 16 + i] = g_qk0[(size_t)s_dst[e] * 16 + i];
    }
    for (int idx = tid; idx < 32 * 24; idx += 256) {
        int e = idx / 24, i = idx % 24;
        s_x1[e * 24 + i]  = feats[(size_t)s_src[e] * 40 + 16 + i];
        s_qk1[e * 24 + i] = g_qk1[(size_t)s_dst[e] * 24 + i];
    }
    __syncthreads();

    // phase 3a: x1s = (x1 . sh)/sqrt3  (256 threads = 32 edges x 8 i)
    {
        int e = tid >> 3, i = tid & 7;
        const float* xp = &s_x1[e * 24 + i * 3];
        s_X0[e * 24 + 16 + i] =
            (xp[0] * s_sh[e * 3] + xp[1] * s_sh[e * 3 + 1] + xp[2] * s_sh[e * 3 + 2]) * INV_SQRT3;
    }
    // phase 3b: H = silu(emb @ W1) for k(32) | v(32) | p(64)
#pragma unroll 1
    for (int r = 0; r < 16; r++) {
        int id = r * 256 + tid;
        int e = id & 31, ch = id >> 5;
        const float* W1; int cc, ld;
        if (ch < 32)      { W1 = W1k; cc = ch;      ld = 32; }
        else if (ch < 64) { W1 = W1v; cc = ch - 32; ld = 32; }
        else              { W1 = W1p; cc = ch - 64; ld = 64; }
        float a = 0.f;
#pragma unroll
        for (int b = 0; b < 10; b++) a += s_emb[e * 10 + b] * __ldg(&W1[b * ld + cc]);
        s_H[e * 128 + ch] = a / (1.f + __expf(-a));
    }
    __syncthreads();

    const int ebase = warp * 4;

    // ===== K path =====
    gemm576(W2k, s_H, 0, s_w, lane, ebase);
    __syncthreads();
#pragma unroll 1
    for (int s4 = 0; s4 < 4; s4++) {
        int e = ebase + s4;
        const float* w  = s_w + e * 576;
        const float* X0 = s_X0 + e * 24;
        float partial = 0.f;
        if (lane < 16) {
            int o = lane;
            float k0 = 0.f;
#pragma unroll
            for (int i = 0; i < 16; i++) k0 += X0[i] * w[i * 16 + o];
#pragma unroll
            for (int i = 0; i < 8; i++)  k0 += X0[16 + i] * w[256 + i * 16 + o];
            partial = k0 * NORM24 * s_qk0[e * 16 + o];
        } else if (lane < 24) {
            int o = lane - 16;
            float xw = 0.f;
#pragma unroll
            for (int i = 0; i < 16; i++) xw += X0[i] * w[384 + i * 8 + o];
            float t = 0.f;
#pragma unroll
            for (int d = 0; d < 3; d++) {
                float k1 = 0.f;
#pragma unroll
                for (int i = 0; i < 8; i++) k1 += s_x1[e * 24 + i * 3 + d] * w[512 + i * 8 + o];
                k1 = (xw * s_sh[e * 3 + d] * INV_SQRT3 + k1) * NORM24;
                t += k1 * s_qk1[e * 24 + o * 3 + d];
            }
            partial = t * INV_SQRT3;
        }
#pragma unroll
        for (int off = 16; off; off >>= 1)
            partial += __shfl_xor_sync(0xffffffffu, partial, off);
        if (lane == 0) {
            float dot = partial * NORM24;
            float ev = s_cut[e] * expf(dot);
            g_expv[e0 + e] = ev;
            atomicAdd(&g_z[s_dst[e]], ev);
        }
    }
    __syncthreads();

    // ===== V path =====
    gemm576(W2v, s_H, 32, s_w, lane, ebase);
    __syncthreads();
#pragma unroll 1
    for (int s4 = 0; s4 < 4; s4++) {
        int e = ebase + s4;
        const float* w  = s_w + e * 576;
        const float* X0 = s_X0 + e * 24;
        float* vf = &g_vflat[(size_t)(e0 + e) * 40];
        if (lane < 16) {
            int o = lane;
            float v0 = 0.f;
#pragma unroll
            for (int i = 0; i < 16; i++) v0 += X0[i] * w[i * 16 + o];
#pragma unroll
            for (int i = 0; i < 8; i++)  v0 += X0[16 + i] * w[256 + i * 16 + o];
            vf[o] = v0 * NORM24;
        } else if (lane < 24) {
            int o = lane - 16;
            float xw = 0.f;
#pragma unroll
            for (int i = 0; i < 16; i++) xw += X0[i] * w[384 + i * 8 + o];
#pragma unroll
            for (int d = 0; d < 3; d++) {
                float v1 = 0.f;
#pragma unroll
                for (int i = 0; i < 8; i++) v1 += s_x1[e * 24 + i * 3 + d] * w[512 + i * 8 + o];
                v1 = (xw * s_sh[e * 3 + d] * INV_SQRT3 + v1) * NORM24;
                vf[16 + o * 3 + d] = v1;
            }
        }
    }
    __syncthreads();

    // ===== P path: only 72 of 1152 W2p columns are live =====
    for (int idx = tid; idx < 64 * 72; idx += 256) {
        int c = idx / 72, j = idx % 72;
        int jj   = (j < 48) ? j : j - 48;
        int base = (j < 48) ? 0 : 512;
        int col  = base + (jj / 3) * 32 + (jj % 3);
        s_w[c * 72 + j] = __ldg(&W2p[c * 1152 + col]);
    }
    __syncthreads();
    {
        float pa0[4] = {0, 0, 0, 0}, pa1[4] = {0, 0, 0, 0}, pa2[4] = {0, 0, 0, 0};
#pragma unroll 2
        for (int c = 0; c < 64; c++) {
            float w0 = s_w[c * 72 + lane];
            float w1 = s_w[c * 72 + 32 + lane];
            float w2 = (lane < 8) ? s_w[c * 72 + 64 + lane] : 0.f;
#pragma unroll
            for (int s4 = 0; s4 < 4; s4++) {
                float h = s_H[(ebase + s4) * 128 + 64 + c];
                pa0[s4] += h * w0; pa1[s4] += h * w1; pa2[s4] += h * w2;
            }
        }
#pragma unroll
        for (int s4 = 0; s4 < 4; s4++) {
            size_t e = (size_t)(e0 + ebase + s4);
            g_wp[e * 72 + lane]      = pa0[s4];
            g_wp[e * 72 + 32 + lane] = pa1[s4];
            if (lane < 8) g_wp[e * 72 + 64 + lane] = pa2[s4];
        }
    }
}

// ---------------- softmax + scatter att ----------------
__global__ void kAttScatter(const int* __restrict__ edst, float* __restrict__ out) {
    int idx = blockIdx.x * blockDim.x + threadIdx.x;
    if (idx >= NEDGE * 40) return;
    int e = idx / 40, j = idx - e * 40;
    int d = edst[e];
    float z = g_z[d];
    float zz = (z == 0.f) ? 1.f : z;
    float alpha = g_expv[e] / zz;
    float coef = (alpha > 0.f) ? sqrtf(alpha) : 0.f;
    if (coef != 0.f)
        atomicAdd(&out[(size_t)d * 40 + j], coef * g_vflat[(size_t)e * 40 + j]);
}

// ---------------- p pass (only p0 cols 0..2 are live) ----------------
__global__ void kPEdge(const int* __restrict__ esrc, const int* __restrict__ edst,
                       const float* __restrict__ att) {
    int e = blockIdx.x * blockDim.x + threadIdx.x;
    if (e >= NEDGE) return;
    int s = esrc[e], d = edst[e];
    const float* a  = &att[(size_t)s * 40];
    const float* wp = &g_wp[(size_t)e * 72];
    float shx = g_sh1[(size_t)e * 3 + 0];
    float shy = g_sh1[(size_t)e * 3 + 1];
    float shz = g_sh1[(size_t)e * 3 + 2];
    float p0 = 0.f, p1 = 0.f, p2 = 0.f;
#pragma unroll
    for (int i = 0; i < 16; i++) {
        float ai = a[i];
        p0 += ai * wp[i * 3 + 0];
        p1 += ai * wp[i * 3 + 1];
        p2 += ai * wp[i * 3 + 2];
    }
#pragma unroll
    for (int i = 0; i < 8; i++) {
        float as = (a[16 + i * 3] * shx + a[16 + i * 3 + 1] * shy + a[16 + i * 3 + 2] * shz) * INV_SQRT3;
        p0 += as * wp[48 + i * 3 + 0];
        p1 += as * wp[48 + i * 3 + 1];
        p2 += as * wp[48 + i * 3 + 2];
    }
    float cw = g_cutw[e] * NORM24;
    atomicAdd(&g_pot3[(size_t)d * 3 + 0], cw * p0);
    atomicAdd(&g_pot3[(size_t)d * 3 + 1], cw * p1);
    atomicAdd(&g_pot3[(size_t)d * 3 + 2], cw * p2);
}

// ---------------- curl fixup ----------------
__global__ void kCurl(float* __restrict__ out) {
    int n = blockIdx.x * blockDim.x + threadIdx.x;
    if (n >= NNODE) return;
    float p0 = g_pot3[(size_t)n * 3 + 0];
    float p1 = g_pot3[(size_t)n * 3 + 1];
    float p2 = g_pot3[(size_t)n * 3 + 2];
    out[(size_t)n * 40 + 0] += 0.1f * (p2 - p1);
    out[(size_t)n * 40 + 1] += 0.1f * (p0 - p2);
    out[(size_t)n * 40 + 2] += 0.1f * (p1 - p0);
}

extern "C" void kernel_launch(void* const* d_in, const int* in_sizes, int n_in,
                              void* d_out, int out_size) {
    const float* feats = (const float*)d_in[0];
    const float* pos   = (const float*)d_in[1];
    const int*   esrc  = (const int*)d_in[2];
    const int*   edst  = (const int*)d_in[3];
    const float* Wq0   = (const float*)d_in[4];
    const float* Wq1   = (const float*)d_in[5];
    const float* W1k   = (const float*)d_in[6];
    const float* W2k   = (const float*)d_in[7];
    const float* W1v   = (const float*)d_in[8];
    const float* W2v   = (const float*)d_in[9];
    const float* Wd00  = (const float*)d_in[10];
    const float* Wd11  = (const float*)d_in[11];
    const float* W1p   = (const float*)d_in[12];
    const float* W2p   = (const float*)d_in[13];
    float* out = (float*)d_out;

    const int smem_bytes = SMEM_FLOATS * 4;
    cudaFuncSetAttribute(kEdgeMain, cudaFuncAttributeMaxDynamicSharedMemorySize, smem_bytes);

    kZero<<<(NNODE * 40 + 255) / 256, 256>>>(out);
    kQK<<<(NNODE + 255) / 256, 256>>>(feats, Wq0, Wq1, Wd00, Wd11);
    kEdgeMain<<<NEDGE / EPB, 256, smem_bytes>>>(feats, pos, esrc, edst,
                                                W1k, W2k, W1v, W2v, W1p, W2p);
    kAttScatter<<<(NEDGE * 40 + 255) / 256, 256>>>(edst, out);
    kPEdge<<<(NEDGE + 255) / 256, 256>>>(esrc, edst, out);
    kCurl<<<(NNODE + 255) / 256, 256>>>(out);
}